// round 9
// baseline (speedup 1.0000x reference)
#include <cuda_runtime.h>
#include <math.h>

// Problem constants
#define NB     32
#define NS     4096
#define ND     2048
#define DH     128
#define LUTN   4096
#define NSPLIT 16
#define SCHUNK (NS / NSPLIT)   // 256

// fp32 constants matching the reference computation
#define PHI_F   1.6180340f                 // (1+sqrt(5))/2 rounded to fp32
#define CONST_C 651.89865f                 // 4096 / (2*pi)
#define STEP_F  0.0015339808f              // (2*pi) / 4096

// Device scratch (no allocations allowed in kernel_launch)
static __device__ float  g_scores[NB * NS];
// transposed partials: g_partial[(b*ND + d) * NSPLIT + c]
static __device__ float  g_partial[NB * ND * NSPLIT];

// ---------------------------------------------------------------------------
// Quantized angle index (identical to reference LUT indexing)
// ---------------------------------------------------------------------------
__device__ __forceinline__ int qidx(float theta)
{
    return __float2int_rd(theta * CONST_C) & (LUTN - 1);
}

// cos(thq)cos(thk) + sin(thq)sin(thk) = cos((idx_q - idx_k) * STEP)
// exact identity on the quantized grid (4096*STEP = 2*pi)
__device__ __forceinline__ float dot_term(float v, float rk, float bk, int iq)
{
    int ik = qidx(fmaf(v, rk, bk));
    return __cosf((float)(iq - ik) * STEP_F);
}

// ---------------------------------------------------------------------------
// Kernel B: scores[b,s] = (1/16) * sum_d cos(theta_q - theta_k) [quantized]
// Loads use DEFAULT caching so the 64 MB head-patch stays in L2 for
// out_partial to re-hit.
// grid: (NS/64, NB), block 256 (8 warps, each warp does 8 rows)
// ---------------------------------------------------------------------------
__global__ void scores_kernel(const float* __restrict__ cs,
                              const float* __restrict__ x,
                              const float* __restrict__ t,
                              const float* __restrict__ wq,
                              const float* __restrict__ bq,
                              const float* __restrict__ wk,
                              const float* __restrict__ bk)
{
    int tid  = threadIdx.x;
    int b    = blockIdx.y;
    int warp = tid >> 5;
    int lane = tid & 31;

    // lane owns d = 4*lane .. 4*lane+3 : compute rk, bk, and q indices locally
    float4 wk4 = *(const float4*)(wk + 4 * lane);
    float4 bk4 = *(const float4*)(bk + 4 * lane);
    float4 rk4 = make_float4(1.0f / (1.0f + fabsf(wk4.x)),
                             1.0f / (1.0f + fabsf(wk4.y)),
                             1.0f / (1.0f + fabsf(wk4.z)),
                             1.0f / (1.0f + fabsf(wk4.w)));

    float4 wq4 = *(const float4*)(wq + 4 * lane);
    float4 bq4 = *(const float4*)(bq + 4 * lane);
    float4 xq  = *(const float4*)(x + (size_t)b * ND + 4 * lane);
    float  tb  = t[b] * PHI_F;

    int iq0 = qidx(fmaf(xq.x, 1.0f / (1.0f + fabsf(wq4.x)), bq4.x + tb));
    int iq1 = qidx(fmaf(xq.y, 1.0f / (1.0f + fabsf(wq4.y)), bq4.y + tb));
    int iq2 = qidx(fmaf(xq.z, 1.0f / (1.0f + fabsf(wq4.z)), bq4.z + tb));
    int iq3 = qidx(fmaf(xq.w, 1.0f / (1.0f + fabsf(wq4.w)), bq4.w + tb));

    const float* base = cs + (size_t)b * NS * ND;
    int s0 = blockIdx.x * 64 + warp * 8;

    #pragma unroll
    for (int r = 0; r < 8; r++) {
        int s = s0 + r;
        // default caching: seed L2 with the head patch for out_partial
        float4 v = *(const float4*)(base + (size_t)s * ND + 4 * lane);
        float part = dot_term(v.x, rk4.x, bk4.x, iq0);
        part      += dot_term(v.y, rk4.y, bk4.y, iq1);
        part      += dot_term(v.z, rk4.z, bk4.z, iq2);
        part      += dot_term(v.w, rk4.w, bk4.w, iq3);
        #pragma unroll
        for (int o = 16; o > 0; o >>= 1)
            part += __shfl_xor_sync(0xFFFFFFFFu, part, o);
        if (lane == 0)
            g_scores[b * NS + s] = part * 0.0625f;  // / sqrt(2*128) = /16
    }
}

// ---------------------------------------------------------------------------
// Kernel C: softmax over S per batch; writes weights straight into d_out
// grid: NB blocks, 512 threads, 8 elements/thread
// ---------------------------------------------------------------------------
__global__ void softmax_kernel(float* __restrict__ wout)
{
    int b   = blockIdx.x;
    int tid = threadIdx.x;
    __shared__ float red[16];

    float v[8];
    float mx = -1e30f;
    #pragma unroll
    for (int j = 0; j < 8; j++) {
        v[j] = g_scores[b * NS + tid + j * 512];
        mx = fmaxf(mx, v[j]);
    }
    #pragma unroll
    for (int o = 16; o > 0; o >>= 1)
        mx = fmaxf(mx, __shfl_xor_sync(0xFFFFFFFFu, mx, o));
    if ((tid & 31) == 0) red[tid >> 5] = mx;
    __syncthreads();
    if (tid < 32) {
        float m = (tid < 16) ? red[tid] : -1e30f;
        #pragma unroll
        for (int o = 8; o > 0; o >>= 1)
            m = fmaxf(m, __shfl_xor_sync(0xFFFFFFFFu, m, o));
        if (tid == 0) red[0] = m;
    }
    __syncthreads();
    mx = red[0];

    float sum = 0.0f;
    #pragma unroll
    for (int j = 0; j < 8; j++) {
        v[j] = __expf(v[j] - mx);
        sum += v[j];
    }
    __syncthreads();
    #pragma unroll
    for (int o = 16; o > 0; o >>= 1)
        sum += __shfl_xor_sync(0xFFFFFFFFu, sum, o);
    if ((tid & 31) == 0) red[tid >> 5] = sum;
    __syncthreads();
    if (tid < 32) {
        float s = (tid < 16) ? red[tid] : 0.0f;
        #pragma unroll
        for (int o = 8; o > 0; o >>= 1)
            s += __shfl_xor_sync(0xFFFFFFFFu, s, o);
        if (tid == 0) red[0] = s;
    }
    __syncthreads();
    float inv = 1.0f / red[0];

    #pragma unroll
    for (int j = 0; j < 8; j++)
        wout[b * NS + tid + j * 512] = v[j] * inv;
}

// ---------------------------------------------------------------------------
// Kernel D: partial[b,d,sc] = sum_{s in chunk} w[b,s] * cs[b,s,d]
// grid: (4 d-tiles, NSPLIT s-chunks, NB batches), block 128 (thread = float4)
// __ldcs: evict-first streaming — its own lines self-evict, preserving the
// scores-seeded head-patch lines in L2 (which dt=0 blocks re-hit).
// Partials stored TRANSPOSED so the reduce kernel reads contiguously.
// ---------------------------------------------------------------------------
__global__ void out_partial_kernel(const float* __restrict__ cs,
                                   const float* __restrict__ wts)
{
    int dt  = blockIdx.x;     // 0..3, 512 floats each
    int sc  = blockIdx.y;     // 0..NSPLIT-1
    int b   = blockIdx.z;
    int tid = threadIdx.x;    // 0..127

    __shared__ float ws[SCHUNK];
    #pragma unroll
    for (int k = 0; k < SCHUNK / 128; k++)
        ws[tid + k * 128] = wts[b * NS + sc * SCHUNK + tid + k * 128];
    __syncthreads();

    const float4* p = (const float4*)(cs + ((size_t)(b * NS + sc * SCHUNK)) * ND
                                         + dt * 512) + tid;
    float4 acc = make_float4(0.f, 0.f, 0.f, 0.f);
    #pragma unroll 8
    for (int s = 0; s < SCHUNK; s++) {
        float w  = ws[s];
        float4 v = __ldcs(p + (size_t)s * (ND / 4));
        acc.x = fmaf(w, v.x, acc.x);
        acc.y = fmaf(w, v.y, acc.y);
        acc.z = fmaf(w, v.z, acc.z);
        acc.w = fmaf(w, v.w, acc.w);
    }
    // transposed store: element (b, d) keeps its NSPLIT partials contiguous
    size_t d0 = (size_t)b * ND + dt * 512 + tid * 4;
    g_partial[(d0 + 0) * NSPLIT + sc] = acc.x;
    g_partial[(d0 + 1) * NSPLIT + sc] = acc.y;
    g_partial[(d0 + 2) * NSPLIT + sc] = acc.z;
    g_partial[(d0 + 3) * NSPLIT + sc] = acc.w;
}

// ---------------------------------------------------------------------------
// Kernel E: deterministic reduction; thread i sums its 16 contiguous partials
// (64 B = 4 independent float4 loads). 65536 threads, fully coalesced.
// ---------------------------------------------------------------------------
__global__ void out_reduce_kernel(float* __restrict__ out)
{
    int i = blockIdx.x * blockDim.x + threadIdx.x;  // 0..NB*ND-1
    const float4* p = (const float4*)(g_partial + (size_t)i * NSPLIT);
    float4 v0 = p[0];
    float4 v1 = p[1];
    float4 v2 = p[2];
    float4 v3 = p[3];
    float s = ((v0.x + v0.y) + (v0.z + v0.w))
            + ((v1.x + v1.y) + (v1.z + v1.w))
            + ((v2.x + v2.y) + (v2.z + v2.w))
            + ((v3.x + v3.y) + (v3.z + v3.w));
    out[i] = s;
}

// ---------------------------------------------------------------------------
extern "C" void kernel_launch(void* const* d_in, const int* in_sizes, int n_in,
                              void* d_out, int out_size)
{
    const float* x  = (const float*)d_in[0];   // (32, 2048)
    const float* cs = (const float*)d_in[1];   // (32, 4096, 2048)
    const float* t  = (const float*)d_in[2];   // (32,)
    const float* wq = (const float*)d_in[3];   // (128,)
    const float* bq = (const float*)d_in[4];   // (128,)
    const float* wk = (const float*)d_in[5];   // (128,)
    const float* bk = (const float*)d_in[6];   // (128,)

    float* out_main = (float*)d_out;            // (32, 2048)
    float* out_wts  = out_main + NB * ND;       // (32, 4096)

    dim3 gS(NS / 64, NB);
    scores_kernel<<<gS, 256>>>(cs, x, t, wq, bq, wk, bk);

    softmax_kernel<<<NB, 512>>>(out_wts);

    dim3 gO(4, NSPLIT, NB);
    out_partial_kernel<<<gO, 128>>>(cs, out_wts);

    out_reduce_kernel<<<(NB * ND) / 256, 256>>>(out_main);
}

// round 12
// speedup vs baseline: 1.0205x; 1.0205x over previous
#include <cuda_runtime.h>
#include <math.h>

// Problem constants
#define NB     32
#define NS     4096
#define ND     2048
#define DH     128
#define LUTN   4096
#define NSPLIT 16
#define SCHUNK (NS / NSPLIT)   // 256

// fp32 constants matching the reference computation
#define PHI_F   1.6180340f                 // (1+sqrt(5))/2 rounded to fp32
#define CONST_C 651.89865f                 // 4096 / (2*pi)
#define STEP_F  0.0015339808f              // (2*pi) / 4096

// Device scratch (no allocations allowed in kernel_launch)
static __device__ float        g_scores[NB * NS];
// contiguous partials: g_partial[(sc*NB + b)*ND + d]  (coalesced writes)
static __device__ float        g_partial[NSPLIT * NB * ND];
// last-block-done tickets, one per (b, dt) slice; zero-initialized, and each
// launch's reducing block resets its own counter -> graph-replay safe.
static __device__ unsigned int g_ticket[NB * 4];

// ---------------------------------------------------------------------------
// Quantized angle index (identical to reference LUT indexing)
// ---------------------------------------------------------------------------
__device__ __forceinline__ int qidx(float theta)
{
    return __float2int_rd(theta * CONST_C) & (LUTN - 1);
}

// cos(thq)cos(thk) + sin(thq)sin(thk) = cos((idx_q - idx_k) * STEP)
// exact identity on the quantized grid (4096*STEP = 2*pi)
__device__ __forceinline__ float dot_term(float v, float rk, float bk, int iq)
{
    int ik = qidx(fmaf(v, rk, bk));
    return __cosf((float)(iq - ik) * STEP_F);
}

// ---------------------------------------------------------------------------
// Kernel B: scores[b,s] = (1/16) * sum_d cos(theta_q - theta_k) [quantized]
// Loads use DEFAULT caching so the 64 MB head-patch stays in L2 for
// out_partial to re-hit.
// grid: (NS/64, NB), block 256 (8 warps, each warp does 8 rows)
// ---------------------------------------------------------------------------
__global__ void scores_kernel(const float* __restrict__ cs,
                              const float* __restrict__ x,
                              const float* __restrict__ t,
                              const float* __restrict__ wq,
                              const float* __restrict__ bq,
                              const float* __restrict__ wk,
                              const float* __restrict__ bk)
{
    int tid  = threadIdx.x;
    int b    = blockIdx.y;
    int warp = tid >> 5;
    int lane = tid & 31;

    // lane owns d = 4*lane .. 4*lane+3 : compute rk, bk, and q indices locally
    float4 wk4 = *(const float4*)(wk + 4 * lane);
    float4 bk4 = *(const float4*)(bk + 4 * lane);
    float4 rk4 = make_float4(1.0f / (1.0f + fabsf(wk4.x)),
                             1.0f / (1.0f + fabsf(wk4.y)),
                             1.0f / (1.0f + fabsf(wk4.z)),
                             1.0f / (1.0f + fabsf(wk4.w)));

    float4 wq4 = *(const float4*)(wq + 4 * lane);
    float4 bq4 = *(const float4*)(bq + 4 * lane);
    float4 xq  = *(const float4*)(x + (size_t)b * ND + 4 * lane);
    float  tb  = t[b] * PHI_F;

    int iq0 = qidx(fmaf(xq.x, 1.0f / (1.0f + fabsf(wq4.x)), bq4.x + tb));
    int iq1 = qidx(fmaf(xq.y, 1.0f / (1.0f + fabsf(wq4.y)), bq4.y + tb));
    int iq2 = qidx(fmaf(xq.z, 1.0f / (1.0f + fabsf(wq4.z)), bq4.z + tb));
    int iq3 = qidx(fmaf(xq.w, 1.0f / (1.0f + fabsf(wq4.w)), bq4.w + tb));

    const float* base = cs + (size_t)b * NS * ND;
    int s0 = blockIdx.x * 64 + warp * 8;

    #pragma unroll
    for (int r = 0; r < 8; r++) {
        int s = s0 + r;
        // default caching: seed L2 with the head patch for out_partial
        float4 v = *(const float4*)(base + (size_t)s * ND + 4 * lane);
        float part = dot_term(v.x, rk4.x, bk4.x, iq0);
        part      += dot_term(v.y, rk4.y, bk4.y, iq1);
        part      += dot_term(v.z, rk4.z, bk4.z, iq2);
        part      += dot_term(v.w, rk4.w, bk4.w, iq3);
        #pragma unroll
        for (int o = 16; o > 0; o >>= 1)
            part += __shfl_xor_sync(0xFFFFFFFFu, part, o);
        if (lane == 0)
            g_scores[b * NS + s] = part * 0.0625f;  // / sqrt(2*128) = /16
    }
}

// ---------------------------------------------------------------------------
// Kernel C: softmax over S per batch; writes weights straight into d_out
// grid: NB blocks, 512 threads, 8 elements/thread
// ---------------------------------------------------------------------------
__global__ void softmax_kernel(float* __restrict__ wout)
{
    int b   = blockIdx.x;
    int tid = threadIdx.x;
    __shared__ float red[16];

    float v[8];
    float mx = -1e30f;
    #pragma unroll
    for (int j = 0; j < 8; j++) {
        v[j] = g_scores[b * NS + tid + j * 512];
        mx = fmaxf(mx, v[j]);
    }
    #pragma unroll
    for (int o = 16; o > 0; o >>= 1)
        mx = fmaxf(mx, __shfl_xor_sync(0xFFFFFFFFu, mx, o));
    if ((tid & 31) == 0) red[tid >> 5] = mx;
    __syncthreads();
    if (tid < 32) {
        float m = (tid < 16) ? red[tid] : -1e30f;
        #pragma unroll
        for (int o = 8; o > 0; o >>= 1)
            m = fmaxf(m, __shfl_xor_sync(0xFFFFFFFFu, m, o));
        if (tid == 0) red[0] = m;
    }
    __syncthreads();
    mx = red[0];

    float sum = 0.0f;
    #pragma unroll
    for (int j = 0; j < 8; j++) {
        v[j] = __expf(v[j] - mx);
        sum += v[j];
    }
    __syncthreads();
    #pragma unroll
    for (int o = 16; o > 0; o >>= 1)
        sum += __shfl_xor_sync(0xFFFFFFFFu, sum, o);
    if ((tid & 31) == 0) red[tid >> 5] = sum;
    __syncthreads();
    if (tid < 32) {
        float s = (tid < 16) ? red[tid] : 0.0f;
        #pragma unroll
        for (int o = 8; o > 0; o >>= 1)
            s += __shfl_xor_sync(0xFFFFFFFFu, s, o);
        if (tid == 0) red[0] = s;
    }
    __syncthreads();
    float inv = 1.0f / red[0];

    #pragma unroll
    for (int j = 0; j < 8; j++)
        wout[b * NS + tid + j * 512] = v[j] * inv;
}

// ---------------------------------------------------------------------------
// Kernel D: partial[sc][b][d] = sum_{s in chunk} w[b,s] * cs[b,s,d]
// plus fused last-block-done reduction into out (no separate reduce launch).
// grid: (4 d-tiles, NSPLIT s-chunks, NB batches), block 128 (thread = float4)
// __ldcs on cs: evict-first streaming preserves the scores-seeded head-patch
// lines in L2 (dt=0 re-hits). Partial writes are contiguous/coalesced.
// Release order: store -> __threadfence -> __syncthreads -> tid0 atomicAdd
// (canonical threadFenceReduction pattern; all 128 threads' stores are
// globally visible before this block's ticket increments).
// ---------------------------------------------------------------------------
__global__ void out_partial_kernel(const float* __restrict__ cs,
                                   const float* __restrict__ wts,
                                   float* __restrict__ out)
{
    int dt  = blockIdx.x;     // 0..3, 512 floats each
    int sc  = blockIdx.y;     // 0..NSPLIT-1
    int b   = blockIdx.z;
    int tid = threadIdx.x;    // 0..127

    __shared__ float ws[SCHUNK];
    __shared__ unsigned int s_ticket;
    #pragma unroll
    for (int k = 0; k < SCHUNK / 128; k++)
        ws[tid + k * 128] = wts[b * NS + sc * SCHUNK + tid + k * 128];
    __syncthreads();

    const float4* p = (const float4*)(cs + ((size_t)(b * NS + sc * SCHUNK)) * ND
                                         + dt * 512) + tid;
    float4 acc = make_float4(0.f, 0.f, 0.f, 0.f);
    #pragma unroll 8
    for (int s = 0; s < SCHUNK; s++) {
        float w  = ws[s];
        float4 v = __ldcs(p + (size_t)s * (ND / 4));
        acc.x = fmaf(w, v.x, acc.x);
        acc.y = fmaf(w, v.y, acc.y);
        acc.z = fmaf(w, v.z, acc.z);
        acc.w = fmaf(w, v.w, acc.w);
    }
    size_t off = (size_t)(sc * NB + b) * ND + dt * 512 + tid * 4;
    *(float4*)(g_partial + off) = acc;

    // ---- last-block-done reduction for this (b, dt) slice ----
    __threadfence();      // make THIS thread's partial store globally visible
    __syncthreads();      // ensure ALL 128 threads have stored + fenced
    if (tid == 0)
        s_ticket = atomicAdd(&g_ticket[b * 4 + dt], 1u);
    __syncthreads();
    if (s_ticket == NSPLIT - 1) {
        // all 16 partials for (b, dt) are globally visible; reduce in fixed
        // c-order (deterministic). __ldcg bypasses L1 (no stale-copy risk).
        size_t base = (size_t)b * ND + dt * 512 + tid * 4;
        float4 a = make_float4(0.f, 0.f, 0.f, 0.f);
        #pragma unroll
        for (int c = 0; c < NSPLIT; c++) {
            float4 v = __ldcg((const float4*)(g_partial
                              + (size_t)c * NB * ND + base));
            a.x += v.x; a.y += v.y; a.z += v.z; a.w += v.w;
        }
        *(float4*)(out + base) = a;
        if (tid == 0)
            g_ticket[b * 4 + dt] = 0u;     // reset for next graph replay
    }
}

// ---------------------------------------------------------------------------
extern "C" void kernel_launch(void* const* d_in, const int* in_sizes, int n_in,
                              void* d_out, int out_size)
{
    const float* x  = (const float*)d_in[0];   // (32, 2048)
    const float* cs = (const float*)d_in[1];   // (32, 4096, 2048)
    const float* t  = (const float*)d_in[2];   // (32,)
    const float* wq = (const float*)d_in[3];   // (128,)
    const float* bq = (const float*)d_in[4];   // (128,)
    const float* wk = (const float*)d_in[5];   // (128,)
    const float* bk = (const float*)d_in[6];   // (128,)

    float* out_main = (float*)d_out;            // (32, 2048)
    float* out_wts  = out_main + NB * ND;       // (32, 4096)

    dim3 gS(NS / 64, NB);
    scores_kernel<<<gS, 256>>>(cs, x, t, wq, bq, wk, bk);

    softmax_kernel<<<NB, 512>>>(out_wts);

    dim3 gO(4, NSPLIT, NB);
    out_partial_kernel<<<gO, 128>>>(cs, out_wts, out_main);
}

// round 13
// speedup vs baseline: 1.0223x; 1.0017x over previous
#include <cuda_runtime.h>
#include <math.h>

// Problem constants
#define NB     32
#define NS     4096
#define ND     2048
#define DH     128
#define LUTN   4096
#define NSPLIT 16
#define SCHUNK (NS / NSPLIT)   // 256

// fp32 constants matching the reference computation
#define PHI_F   1.6180340f                 // (1+sqrt(5))/2 rounded to fp32
#define CONST_C 651.89865f                 // 4096 / (2*pi)
#define STEP_F  0.0015339808f              // (2*pi) / 4096

// Device scratch (no allocations allowed in kernel_launch)
static __device__ float        g_scores[NB * NS];
// contiguous partials: g_partial[(sc*NB + b)*ND + d]  (coalesced writes)
static __device__ float        g_partial[NSPLIT * NB * ND];
// last-block-done tickets, one per (b, dt) slice; zero-initialized, and each
// launch's reducing block resets its own counter -> graph-replay safe.
static __device__ unsigned int g_ticket[NB * 4];

// ---------------------------------------------------------------------------
// Quantized angle index (identical to reference LUT indexing)
// ---------------------------------------------------------------------------
__device__ __forceinline__ int qidx(float theta)
{
    return __float2int_rd(theta * CONST_C) & (LUTN - 1);
}

// cos(thq)cos(thk) + sin(thq)sin(thk) = cos((iq - ik) * STEP)
// cos is 2pi-periodic on the 4096-grid -> no masking of ik needed.
// rkC/bkC are pre-scaled by CONST_C so one FFMA yields the grid coordinate.
__device__ __forceinline__ float dot_term(float v, float rkC, float bkC,
                                          float angq)
{
    float f  = fmaf(v, rkC, bkC);          // theta * CONST_C
    int   ik = __float2int_rd(f);          // floor -> raw index
    return __cosf(fmaf((float)ik, -STEP_F, angq));
}

// ---------------------------------------------------------------------------
// Kernel B: scores[b,s] = (1/16) * sum_d cos(theta_q - theta_k) [quantized]
// Loads use DEFAULT caching so the 64 MB head-patch stays in L2 for
// out_partial to re-hit.
// grid: (NS/64, NB), block 256 (8 warps, each warp does 8 rows)
// ---------------------------------------------------------------------------
__global__ void scores_kernel(const float* __restrict__ cs,
                              const float* __restrict__ x,
                              const float* __restrict__ t,
                              const float* __restrict__ wq,
                              const float* __restrict__ bq,
                              const float* __restrict__ wk,
                              const float* __restrict__ bk)
{
    int tid  = threadIdx.x;
    int b    = blockIdx.y;
    int warp = tid >> 5;
    int lane = tid & 31;

    // lane owns d = 4*lane .. 4*lane+3 : precompute scaled key params and
    // quantized query angles locally
    float4 wk4 = *(const float4*)(wk + 4 * lane);
    float4 bk4 = *(const float4*)(bk + 4 * lane);
    float4 rkC = make_float4(CONST_C / (1.0f + fabsf(wk4.x)),
                             CONST_C / (1.0f + fabsf(wk4.y)),
                             CONST_C / (1.0f + fabsf(wk4.z)),
                             CONST_C / (1.0f + fabsf(wk4.w)));
    float4 bkC = make_float4(bk4.x * CONST_C, bk4.y * CONST_C,
                             bk4.z * CONST_C, bk4.w * CONST_C);

    float4 wq4 = *(const float4*)(wq + 4 * lane);
    float4 bq4 = *(const float4*)(bq + 4 * lane);
    float4 xq  = *(const float4*)(x + (size_t)b * ND + 4 * lane);
    float  tb  = t[b] * PHI_F;

    // masked query indices (matches reference exactly), as grid angles
    float aq0 = (float)qidx(fmaf(xq.x, 1.0f / (1.0f + fabsf(wq4.x)), bq4.x + tb)) * STEP_F;
    float aq1 = (float)qidx(fmaf(xq.y, 1.0f / (1.0f + fabsf(wq4.y)), bq4.y + tb)) * STEP_F;
    float aq2 = (float)qidx(fmaf(xq.z, 1.0f / (1.0f + fabsf(wq4.z)), bq4.z + tb)) * STEP_F;
    float aq3 = (float)qidx(fmaf(xq.w, 1.0f / (1.0f + fabsf(wq4.w)), bq4.w + tb)) * STEP_F;

    const float* base = cs + (size_t)b * NS * ND;
    int s0 = blockIdx.x * 64 + warp * 8;

    #pragma unroll
    for (int r = 0; r < 8; r++) {
        int s = s0 + r;
        // default caching: seed L2 with the head patch for out_partial
        float4 v = *(const float4*)(base + (size_t)s * ND + 4 * lane);
        float part = dot_term(v.x, rkC.x, bkC.x, aq0);
        part      += dot_term(v.y, rkC.y, bkC.y, aq1);
        part      += dot_term(v.z, rkC.z, bkC.z, aq2);
        part      += dot_term(v.w, rkC.w, bkC.w, aq3);
        #pragma unroll
        for (int o = 16; o > 0; o >>= 1)
            part += __shfl_xor_sync(0xFFFFFFFFu, part, o);
        if (lane == 0)
            g_scores[b * NS + s] = part * 0.0625f;  // / sqrt(2*128) = /16
    }
}

// ---------------------------------------------------------------------------
// Kernel C: softmax over S per batch; writes weights straight into d_out
// grid: NB blocks, 512 threads, 8 elements/thread
// ---------------------------------------------------------------------------
__global__ void softmax_kernel(float* __restrict__ wout)
{
    int b   = blockIdx.x;
    int tid = threadIdx.x;
    __shared__ float red[16];

    float v[8];
    float mx = -1e30f;
    #pragma unroll
    for (int j = 0; j < 8; j++) {
        v[j] = g_scores[b * NS + tid + j * 512];
        mx = fmaxf(mx, v[j]);
    }
    #pragma unroll
    for (int o = 16; o > 0; o >>= 1)
        mx = fmaxf(mx, __shfl_xor_sync(0xFFFFFFFFu, mx, o));
    if ((tid & 31) == 0) red[tid >> 5] = mx;
    __syncthreads();
    if (tid < 32) {
        float m = (tid < 16) ? red[tid] : -1e30f;
        #pragma unroll
        for (int o = 8; o > 0; o >>= 1)
            m = fmaxf(m, __shfl_xor_sync(0xFFFFFFFFu, m, o));
        if (tid == 0) red[0] = m;
    }
    __syncthreads();
    mx = red[0];

    float sum = 0.0f;
    #pragma unroll
    for (int j = 0; j < 8; j++) {
        v[j] = __expf(v[j] - mx);
        sum += v[j];
    }
    __syncthreads();
    #pragma unroll
    for (int o = 16; o > 0; o >>= 1)
        sum += __shfl_xor_sync(0xFFFFFFFFu, sum, o);
    if ((tid & 31) == 0) red[tid >> 5] = sum;
    __syncthreads();
    if (tid < 32) {
        float s = (tid < 16) ? red[tid] : 0.0f;
        #pragma unroll
        for (int o = 8; o > 0; o >>= 1)
            s += __shfl_xor_sync(0xFFFFFFFFu, s, o);
        if (tid == 0) red[0] = s;
    }
    __syncthreads();
    float inv = 1.0f / red[0];

    #pragma unroll
    for (int j = 0; j < 8; j++)
        wout[b * NS + tid + j * 512] = v[j] * inv;
}

// ---------------------------------------------------------------------------
// Kernel D: partial[sc][b][d] = sum_{s in chunk} w[b,s] * cs[b,s,d]
// plus fused last-block-done reduction into out (no separate reduce launch).
// grid: (4 d-tiles, NSPLIT s-chunks, NB batches), block 128 (thread = float4)
// __ldcs on cs: evict-first streaming preserves the scores-seeded head-patch
// lines in L2 (dt=0 re-hits). Partial writes are contiguous/coalesced.
// Release order: store -> __threadfence -> __syncthreads -> tid0 atomicAdd
// (canonical threadFenceReduction pattern).
// ---------------------------------------------------------------------------
__global__ void out_partial_kernel(const float* __restrict__ cs,
                                   const float* __restrict__ wts,
                                   float* __restrict__ out)
{
    int dt  = blockIdx.x;     // 0..3, 512 floats each
    int sc  = blockIdx.y;     // 0..NSPLIT-1
    int b   = blockIdx.z;
    int tid = threadIdx.x;    // 0..127

    __shared__ float ws[SCHUNK];
    __shared__ unsigned int s_ticket;
    #pragma unroll
    for (int k = 0; k < SCHUNK / 128; k++)
        ws[tid + k * 128] = wts[b * NS + sc * SCHUNK + tid + k * 128];
    __syncthreads();

    const float4* p = (const float4*)(cs + ((size_t)(b * NS + sc * SCHUNK)) * ND
                                         + dt * 512) + tid;
    float4 acc = make_float4(0.f, 0.f, 0.f, 0.f);
    #pragma unroll 8
    for (int s = 0; s < SCHUNK; s++) {
        float w  = ws[s];
        float4 v = __ldcs(p + (size_t)s * (ND / 4));
        acc.x = fmaf(w, v.x, acc.x);
        acc.y = fmaf(w, v.y, acc.y);
        acc.z = fmaf(w, v.z, acc.z);
        acc.w = fmaf(w, v.w, acc.w);
    }
    size_t off = (size_t)(sc * NB + b) * ND + dt * 512 + tid * 4;
    *(float4*)(g_partial + off) = acc;

    // ---- last-block-done reduction for this (b, dt) slice ----
    __threadfence();      // make THIS thread's partial store globally visible
    __syncthreads();      // ensure ALL 128 threads have stored + fenced
    if (tid == 0)
        s_ticket = atomicAdd(&g_ticket[b * 4 + dt], 1u);
    __syncthreads();
    if (s_ticket == NSPLIT - 1) {
        // all 16 partials for (b, dt) are globally visible; reduce in fixed
        // c-order (deterministic). __ldcg bypasses L1 (no stale-copy risk).
        size_t base = (size_t)b * ND + dt * 512 + tid * 4;
        float4 a = make_float4(0.f, 0.f, 0.f, 0.f);
        #pragma unroll
        for (int c = 0; c < NSPLIT; c++) {
            float4 v = __ldcg((const float4*)(g_partial
                              + (size_t)c * NB * ND + base));
            a.x += v.x; a.y += v.y; a.z += v.z; a.w += v.w;
        }
        *(float4*)(out + base) = a;
        if (tid == 0)
            g_ticket[b * 4 + dt] = 0u;     // reset for next graph replay
    }
}

// ---------------------------------------------------------------------------
extern "C" void kernel_launch(void* const* d_in, const int* in_sizes, int n_in,
                              void* d_out, int out_size)
{
    const float* x  = (const float*)d_in[0];   // (32, 2048)
    const float* cs = (const float*)d_in[1];   // (32, 4096, 2048)
    const float* t  = (const float*)d_in[2];   // (32,)
    const float* wq = (const float*)d_in[3];   // (128,)
    const float* bq = (const float*)d_in[4];   // (128,)
    const float* wk = (const float*)d_in[5];   // (128,)
    const float* bk = (const float*)d_in[6];   // (128,)

    float* out_main = (float*)d_out;            // (32, 2048)
    float* out_wts  = out_main + NB * ND;       // (32, 4096)

    dim3 gS(NS / 64, NB);
    scores_kernel<<<gS, 256>>>(cs, x, t, wq, bq, wk, bk);

    softmax_kernel<<<NB, 512>>>(out_wts);

    dim3 gO(4, NSPLIT, NB);
    out_partial_kernel<<<gO, 128>>>(cs, out_wts, out_main);
}

// round 14
// speedup vs baseline: 1.0351x; 1.0125x over previous
#include <cuda_runtime.h>
#include <math.h>

// Problem constants
#define NB     32
#define NS     4096
#define ND     2048
#define DH     128
#define LUTN   4096
#define NSPLIT 16
#define SCHUNK (NS / NSPLIT)   // 256

// fp32 constants matching the reference computation
#define PHI_F   1.6180340f                 // (1+sqrt(5))/2 rounded to fp32
#define CONST_C 651.89865f                 // 4096 / (2*pi)
#define STEP_F  0.0015339808f              // (2*pi) / 4096
#define MAGIC_F 12582912.0f                // 1.5 * 2^23 (RN rounding shift)

// Device scratch (no allocations allowed in kernel_launch)
static __device__ float        g_scores[NB * NS];
// contiguous partials: g_partial[(sc*NB + b)*ND + d]  (coalesced writes)
static __device__ float        g_partial[NSPLIT * NB * ND];
// last-block-done tickets, one per (b, dt) slice; zero-initialized, and each
// launch's reducing block resets its own counter -> graph-replay safe.
static __device__ unsigned int g_ticket[NB * 4];

// ---------------------------------------------------------------------------
// Quantized angle index (identical to reference LUT indexing)
// ---------------------------------------------------------------------------
__device__ __forceinline__ int qidx(float theta)
{
    return __float2int_rd(theta * CONST_C) & (LUTN - 1);
}

// cos(thq)cos(thk) + sin(thq)sin(thk) = cos((iq - ik) * STEP)
// cos is 2pi-periodic on the 4096-grid -> no masking of ik needed.
// floor via the magic-number RN trick: rn(f - 0.5) == floor(f) (the -0.5 is
// pre-folded into bkC2). Keeps the whole chain on the fma pipe; only the
// final cos touches MUFU.
__device__ __forceinline__ float dot_term(float v, float rkC, float bkC2,
                                          float angq)
{
    float f  = fmaf(v, rkC, bkC2);         // theta*C - 0.5
    float tm = f + MAGIC_F;                // RN -> MAGIC + floor(theta*C)
    float fr = tm - MAGIC_F;               // floor(theta*C) as float
    return __cosf(fmaf(fr, -STEP_F, angq));
}

// ---------------------------------------------------------------------------
// Kernel B: scores[b,s] = (1/16) * sum_d cos(theta_q - theta_k) [quantized]
// Loads use DEFAULT caching so the 64 MB head-patch stays in L2 for
// out_partial to re-hit.
// grid: (NS/64, NB), block 256 (8 warps, each warp does 8 rows)
// ---------------------------------------------------------------------------
__global__ void scores_kernel(const float* __restrict__ cs,
                              const float* __restrict__ x,
                              const float* __restrict__ t,
                              const float* __restrict__ wq,
                              const float* __restrict__ bq,
                              const float* __restrict__ wk,
                              const float* __restrict__ bk)
{
    int tid  = threadIdx.x;
    int b    = blockIdx.y;
    int warp = tid >> 5;
    int lane = tid & 31;

    // lane owns d = 4*lane .. 4*lane+3 : precompute scaled key params and
    // quantized query angles locally
    float4 wk4 = *(const float4*)(wk + 4 * lane);
    float4 bk4 = *(const float4*)(bk + 4 * lane);
    float4 rkC = make_float4(CONST_C / (1.0f + fabsf(wk4.x)),
                             CONST_C / (1.0f + fabsf(wk4.y)),
                             CONST_C / (1.0f + fabsf(wk4.z)),
                             CONST_C / (1.0f + fabsf(wk4.w)));
    // bk*C with the floor-trick's -0.5 pre-folded in
    float4 bkC2 = make_float4(fmaf(bk4.x, CONST_C, -0.5f),
                              fmaf(bk4.y, CONST_C, -0.5f),
                              fmaf(bk4.z, CONST_C, -0.5f),
                              fmaf(bk4.w, CONST_C, -0.5f));

    float4 wq4 = *(const float4*)(wq + 4 * lane);
    float4 bq4 = *(const float4*)(bq + 4 * lane);
    float4 xq  = *(const float4*)(x + (size_t)b * ND + 4 * lane);
    float  tb  = t[b] * PHI_F;

    // masked query indices (matches reference exactly), as grid angles
    float aq0 = (float)qidx(fmaf(xq.x, 1.0f / (1.0f + fabsf(wq4.x)), bq4.x + tb)) * STEP_F;
    float aq1 = (float)qidx(fmaf(xq.y, 1.0f / (1.0f + fabsf(wq4.y)), bq4.y + tb)) * STEP_F;
    float aq2 = (float)qidx(fmaf(xq.z, 1.0f / (1.0f + fabsf(wq4.z)), bq4.z + tb)) * STEP_F;
    float aq3 = (float)qidx(fmaf(xq.w, 1.0f / (1.0f + fabsf(wq4.w)), bq4.w + tb)) * STEP_F;

    const float* base = cs + (size_t)b * NS * ND;
    int s0 = blockIdx.x * 64 + warp * 8;

    #pragma unroll
    for (int r = 0; r < 8; r++) {
        int s = s0 + r;
        // default caching: seed L2 with the head patch for out_partial
        float4 v = *(const float4*)(base + (size_t)s * ND + 4 * lane);
        float p0 = dot_term(v.x, rkC.x, bkC2.x, aq0);
        float p1 = dot_term(v.y, rkC.y, bkC2.y, aq1);
        float p2 = dot_term(v.z, rkC.z, bkC2.z, aq2);
        float p3 = dot_term(v.w, rkC.w, bkC2.w, aq3);
        float part = (p0 + p1) + (p2 + p3);
        #pragma unroll
        for (int o = 16; o > 0; o >>= 1)
            part += __shfl_xor_sync(0xFFFFFFFFu, part, o);
        if (lane == 0)
            g_scores[b * NS + s] = part * 0.0625f;  // / sqrt(2*128) = /16
    }
}

// ---------------------------------------------------------------------------
// Kernel C: softmax over S per batch; writes weights straight into d_out
// grid: NB blocks, 512 threads, 8 elements/thread
// ---------------------------------------------------------------------------
__global__ void softmax_kernel(float* __restrict__ wout)
{
    int b   = blockIdx.x;
    int tid = threadIdx.x;
    __shared__ float red[16];

    float v[8];
    float mx = -1e30f;
    #pragma unroll
    for (int j = 0; j < 8; j++) {
        v[j] = g_scores[b * NS + tid + j * 512];
        mx = fmaxf(mx, v[j]);
    }
    #pragma unroll
    for (int o = 16; o > 0; o >>= 1)
        mx = fmaxf(mx, __shfl_xor_sync(0xFFFFFFFFu, mx, o));
    if ((tid & 31) == 0) red[tid >> 5] = mx;
    __syncthreads();
    if (tid < 32) {
        float m = (tid < 16) ? red[tid] : -1e30f;
        #pragma unroll
        for (int o = 8; o > 0; o >>= 1)
            m = fmaxf(m, __shfl_xor_sync(0xFFFFFFFFu, m, o));
        if (tid == 0) red[0] = m;
    }
    __syncthreads();
    mx = red[0];

    float sum = 0.0f;
    #pragma unroll
    for (int j = 0; j < 8; j++) {
        v[j] = __expf(v[j] - mx);
        sum += v[j];
    }
    __syncthreads();
    #pragma unroll
    for (int o = 16; o > 0; o >>= 1)
        sum += __shfl_xor_sync(0xFFFFFFFFu, sum, o);
    if ((tid & 31) == 0) red[tid >> 5] = sum;
    __syncthreads();
    if (tid < 32) {
        float s = (tid < 16) ? red[tid] : 0.0f;
        #pragma unroll
        for (int o = 8; o > 0; o >>= 1)
            s += __shfl_xor_sync(0xFFFFFFFFu, s, o);
        if (tid == 0) red[0] = s;
    }
    __syncthreads();
    float inv = 1.0f / red[0];

    #pragma unroll
    for (int j = 0; j < 8; j++)
        wout[b * NS + tid + j * 512] = v[j] * inv;
}

// ---------------------------------------------------------------------------
// Kernel D: partial[sc][b][d] = sum_{s in chunk} w[b,s] * cs[b,s,d]
// plus fused last-block-done reduction into out (no separate reduce launch).
// grid: (4 d-tiles, NSPLIT s-chunks, NB batches), block 128 (thread = float4)
// __ldcs on cs: evict-first streaming preserves the scores-seeded head-patch
// lines in L2 (dt=0 re-hits). Partial writes are contiguous/coalesced.
// Release order: store -> __threadfence -> __syncthreads -> tid0 atomicAdd
// (canonical threadFenceReduction pattern).
// ---------------------------------------------------------------------------
__global__ void out_partial_kernel(const float* __restrict__ cs,
                                   const float* __restrict__ wts,
                                   float* __restrict__ out)
{
    int dt  = blockIdx.x;     // 0..3, 512 floats each
    int sc  = blockIdx.y;     // 0..NSPLIT-1
    int b   = blockIdx.z;
    int tid = threadIdx.x;    // 0..127

    __shared__ float ws[SCHUNK];
    __shared__ unsigned int s_ticket;
    #pragma unroll
    for (int k = 0; k < SCHUNK / 128; k++)
        ws[tid + k * 128] = wts[b * NS + sc * SCHUNK + tid + k * 128];
    __syncthreads();

    const float4* p = (const float4*)(cs + ((size_t)(b * NS + sc * SCHUNK)) * ND
                                         + dt * 512) + tid;
    float4 acc = make_float4(0.f, 0.f, 0.f, 0.f);
    #pragma unroll 8
    for (int s = 0; s < SCHUNK; s++) {
        float w  = ws[s];
        float4 v = __ldcs(p + (size_t)s * (ND / 4));
        acc.x = fmaf(w, v.x, acc.x);
        acc.y = fmaf(w, v.y, acc.y);
        acc.z = fmaf(w, v.z, acc.z);
        acc.w = fmaf(w, v.w, acc.w);
    }
    size_t off = (size_t)(sc * NB + b) * ND + dt * 512 + tid * 4;
    *(float4*)(g_partial + off) = acc;

    // ---- last-block-done reduction for this (b, dt) slice ----
    __threadfence();      // make THIS thread's partial store globally visible
    __syncthreads();      // ensure ALL 128 threads have stored + fenced
    if (tid == 0)
        s_ticket = atomicAdd(&g_ticket[b * 4 + dt], 1u);
    __syncthreads();
    if (s_ticket == NSPLIT - 1) {
        // all 16 partials for (b, dt) are globally visible; reduce in fixed
        // c-order (deterministic). __ldcg bypasses L1 (no stale-copy risk).
        size_t base = (size_t)b * ND + dt * 512 + tid * 4;
        float4 a = make_float4(0.f, 0.f, 0.f, 0.f);
        #pragma unroll
        for (int c = 0; c < NSPLIT; c++) {
            float4 v = __ldcg((const float4*)(g_partial
                              + (size_t)c * NB * ND + base));
            a.x += v.x; a.y += v.y; a.z += v.z; a.w += v.w;
        }
        *(float4*)(out + base) = a;
        if (tid == 0)
            g_ticket[b * 4 + dt] = 0u;     // reset for next graph replay
    }
}

// ---------------------------------------------------------------------------
extern "C" void kernel_launch(void* const* d_in, const int* in_sizes, int n_in,
                              void* d_out, int out_size)
{
    const float* x  = (const float*)d_in[0];   // (32, 2048)
    const float* cs = (const float*)d_in[1];   // (32, 4096, 2048)
    const float* t  = (const float*)d_in[2];   // (32,)
    const float* wq = (const float*)d_in[3];   // (128,)
    const float* bq = (const float*)d_in[4];   // (128,)
    const float* wk = (const float*)d_in[5];   // (128,)
    const float* bk = (const float*)d_in[6];   // (128,)

    float* out_main = (float*)d_out;            // (32, 2048)
    float* out_wts  = out_main + NB * ND;       // (32, 4096)

    dim3 gS(NS / 64, NB);
    scores_kernel<<<gS, 256>>>(cs, x, t, wq, bq, wk, bk);

    softmax_kernel<<<NB, 512>>>(out_wts);

    dim3 gO(4, NSPLIT, NB);
    out_partial_kernel<<<gO, 128>>>(cs, out_wts, out_main);
}